// round 1
// baseline (speedup 1.0000x reference)
#include <cuda_runtime.h>
#include <cuda_bf16.h>

#define N_NODES 100000
#define N_EDGES 1600000
#define IN_C    128
#define HID_C   128
#define OUT_C   64

// Scratch (no allocations allowed -> __device__ globals)
__device__ float g_hs1 [(size_t)N_NODES * HID_C];  // inv[s]*h1[s]  (gather source, layer 1)
__device__ float g_acc1[(size_t)N_NODES * HID_C];  // accumulator, init = hs1 (self loop)
__device__ float g_hs2 [(size_t)N_NODES * OUT_C];  // inv[s]*h2[s]  (gather source, layer 2)
__device__ int   g_deg [N_NODES];
__device__ float g_inv [N_NODES];
__device__ int   g_is32;                           // edge_index dtype flag (0=int64, 1=int32)

// ---------------------------------------------------------------------------
// helpers
// ---------------------------------------------------------------------------
__device__ __forceinline__ void red_add_v4(float* addr, float4 v) {
    asm volatile("red.global.add.v4.f32 [%0], {%1,%2,%3,%4};"
                 :: "l"(addr), "f"(v.x), "f"(v.y), "f"(v.z), "f"(v.w)
                 : "memory");
}

__device__ __forceinline__ int edge_val(const void* ei, int is32, long long idx) {
    if (is32) return ((const int*)ei)[idx];
    return (int)(((const long long*)ei)[idx]);
}

// ---------------------------------------------------------------------------
// setup kernels
// ---------------------------------------------------------------------------
__global__ void k_initdeg() {
    int i = blockIdx.x * blockDim.x + threadIdx.x;
    if (i < N_NODES) g_deg[i] = 1;   // self-loop
    if (i == 0) g_is32 = 0;
}

// Detect whether edge_index is int64 or int32: reading int32 data as int64
// packs two random indices into one word -> value >= N_NODES almost surely.
__global__ void k_detect(const long long* __restrict__ ei) {
    int i = blockIdx.x * blockDim.x + threadIdx.x;
    if (i < 4096) {
        long long v = ei[i];
        if (v < 0 || v >= N_NODES) g_is32 = 1;
    }
}

__global__ void k_count(const void* __restrict__ ei) {
    int e = blockIdx.x * blockDim.x + threadIdx.x;
    if (e < N_EDGES) {
        int d = edge_val(ei, g_is32, (long long)N_EDGES + e);
        atomicAdd(&g_deg[d], 1);
    }
}

__global__ void k_inv() {
    int i = blockIdx.x * blockDim.x + threadIdx.x;
    if (i < N_NODES) g_inv[i] = rsqrtf((float)g_deg[i]);
}

// ---------------------------------------------------------------------------
// GEMM1: h1 = X @ W1 ; epilogue: hs1 = inv[row]*h1 ; acc1 = hs1 (self loop)
// Block tile 128x128, 256 threads, 8x8 micro-tile (strided: row=ty+16i, col=tx+16j)
// ---------------------------------------------------------------------------
__global__ __launch_bounds__(256) void k_gemm1(const float* __restrict__ X,
                                               const float* __restrict__ W) {
    __shared__ float As[128][33];
    __shared__ float Bs[32][128];
    const int tid = threadIdx.x;
    const int tx = tid & 15, ty = tid >> 4;
    const int blockRow = blockIdx.x * 128;
    float acc[8][8];
    #pragma unroll
    for (int i = 0; i < 8; i++)
        #pragma unroll
        for (int j = 0; j < 8; j++) acc[i][j] = 0.f;

    for (int kc = 0; kc < IN_C; kc += 32) {
        // A tile: 128 rows x 32 k
        #pragma unroll
        for (int it = 0; it < 4; it++) {
            int idx = tid + it * 256;          // 0..1023
            int r = idx >> 3, c4 = idx & 7;
            int row = blockRow + r;
            float4 v = make_float4(0.f, 0.f, 0.f, 0.f);
            if (row < N_NODES)
                v = *(const float4*)(X + (size_t)row * IN_C + kc + c4 * 4);
            As[r][c4 * 4 + 0] = v.x; As[r][c4 * 4 + 1] = v.y;
            As[r][c4 * 4 + 2] = v.z; As[r][c4 * 4 + 3] = v.w;
        }
        // B tile: 32 k x 128 cols
        #pragma unroll
        for (int it = 0; it < 4; it++) {
            int idx = tid + it * 256;
            int r = idx >> 5, c4 = idx & 31;
            *(float4*)&Bs[r][c4 * 4] =
                *(const float4*)(W + (size_t)(kc + r) * HID_C + c4 * 4);
        }
        __syncthreads();
        #pragma unroll
        for (int k = 0; k < 32; k++) {
            float a[8], b[8];
            #pragma unroll
            for (int i = 0; i < 8; i++) a[i] = As[ty + 16 * i][k];
            #pragma unroll
            for (int j = 0; j < 8; j++) b[j] = Bs[k][tx + 16 * j];
            #pragma unroll
            for (int i = 0; i < 8; i++)
                #pragma unroll
                for (int j = 0; j < 8; j++) acc[i][j] += a[i] * b[j];
        }
        __syncthreads();
    }

    #pragma unroll
    for (int i = 0; i < 8; i++) {
        int row = blockRow + ty + 16 * i;
        if (row < N_NODES) {
            float iv = g_inv[row];
            #pragma unroll
            for (int j = 0; j < 8; j++) {
                int col = tx + 16 * j;
                float v = iv * acc[i][j];
                g_hs1 [(size_t)row * HID_C + col] = v;
                g_acc1[(size_t)row * HID_C + col] = v;
            }
        }
    }
}

// ---------------------------------------------------------------------------
// Scatter layer 1: acc1[dst] += hs1[src]   (one warp per edge, float4 RED)
// ---------------------------------------------------------------------------
__global__ __launch_bounds__(256) void k_scatter1(const void* __restrict__ ei) {
    long long gid = (long long)blockIdx.x * blockDim.x + threadIdx.x;
    int e = (int)(gid >> 5);
    int lane = threadIdx.x & 31;
    if (e >= N_EDGES) return;
    int is32 = g_is32;
    int s = edge_val(ei, is32, e);
    int d = edge_val(ei, is32, (long long)N_EDGES + e);
    float4 v = *(const float4*)(g_hs1 + (size_t)s * HID_C + lane * 4);
    red_add_v4(g_acc1 + (size_t)d * HID_C + lane * 4, v);
}

// ---------------------------------------------------------------------------
// GEMM2: A = relu(inv[row]*acc1[row] + b1)  (fused into A-tile load)
//        h2 = A @ W2 ; epilogue: hs2 = inv[row]*h2 ; out = hs2 (self loop init)
// Block tile 128x64, 256 threads, 8x4 micro-tile
// ---------------------------------------------------------------------------
__global__ __launch_bounds__(256) void k_gemm2(const float* __restrict__ W2,
                                               const float* __restrict__ b1,
                                               float* __restrict__ out) {
    __shared__ float As[128][33];
    __shared__ float Bs[32][64];
    const int tid = threadIdx.x;
    const int tx = tid & 15, ty = tid >> 4;
    const int blockRow = blockIdx.x * 128;
    float acc[8][4];
    #pragma unroll
    for (int i = 0; i < 8; i++)
        #pragma unroll
        for (int j = 0; j < 4; j++) acc[i][j] = 0.f;

    for (int kc = 0; kc < HID_C; kc += 32) {
        #pragma unroll
        for (int it = 0; it < 4; it++) {
            int idx = tid + it * 256;
            int r = idx >> 3, c4 = idx & 7;
            int row = blockRow + r;
            float4 v = make_float4(0.f, 0.f, 0.f, 0.f);
            if (row < N_NODES) {
                v = *(const float4*)(g_acc1 + (size_t)row * HID_C + kc + c4 * 4);
                float iv = g_inv[row];
                float4 bb = *(const float4*)(b1 + kc + c4 * 4);
                v.x = fmaxf(iv * v.x + bb.x, 0.f);
                v.y = fmaxf(iv * v.y + bb.y, 0.f);
                v.z = fmaxf(iv * v.z + bb.z, 0.f);
                v.w = fmaxf(iv * v.w + bb.w, 0.f);
            }
            As[r][c4 * 4 + 0] = v.x; As[r][c4 * 4 + 1] = v.y;
            As[r][c4 * 4 + 2] = v.z; As[r][c4 * 4 + 3] = v.w;
        }
        // B tile: 32 x 64 = 512 float4
        #pragma unroll
        for (int it = 0; it < 2; it++) {
            int idx = tid + it * 256;          // 0..511
            int r = idx >> 4, c4 = idx & 15;
            *(float4*)&Bs[r][c4 * 4] =
                *(const float4*)(W2 + (size_t)(kc + r) * OUT_C + c4 * 4);
        }
        __syncthreads();
        #pragma unroll
        for (int k = 0; k < 32; k++) {
            float a[8], b[4];
            #pragma unroll
            for (int i = 0; i < 8; i++) a[i] = As[ty + 16 * i][k];
            #pragma unroll
            for (int j = 0; j < 4; j++) b[j] = Bs[k][tx + 16 * j];
            #pragma unroll
            for (int i = 0; i < 8; i++)
                #pragma unroll
                for (int j = 0; j < 4; j++) acc[i][j] += a[i] * b[j];
        }
        __syncthreads();
    }

    #pragma unroll
    for (int i = 0; i < 8; i++) {
        int row = blockRow + ty + 16 * i;
        if (row < N_NODES) {
            float iv = g_inv[row];
            #pragma unroll
            for (int j = 0; j < 4; j++) {
                int col = tx + 16 * j;
                float v = iv * acc[i][j];
                g_hs2[(size_t)row * OUT_C + col] = v;
                out  [(size_t)row * OUT_C + col] = v;
            }
        }
    }
}

// ---------------------------------------------------------------------------
// Scatter layer 2: out[dst] += hs2[src]   (16 threads per edge, float4 RED)
// ---------------------------------------------------------------------------
__global__ __launch_bounds__(256) void k_scatter2(const void* __restrict__ ei,
                                                  float* __restrict__ out) {
    long long gid = (long long)blockIdx.x * blockDim.x + threadIdx.x;
    int e = (int)(gid >> 4);
    int l = threadIdx.x & 15;
    if (e >= N_EDGES) return;
    int is32 = g_is32;
    int s = edge_val(ei, is32, e);
    int d = edge_val(ei, is32, (long long)N_EDGES + e);
    float4 v = *(const float4*)(g_hs2 + (size_t)s * OUT_C + l * 4);
    red_add_v4(out + (size_t)d * OUT_C + l * 4, v);
}

// ---------------------------------------------------------------------------
// Final: out = inv[node] * out + b2
// ---------------------------------------------------------------------------
__global__ void k_final(float* __restrict__ out, const float* __restrict__ b2) {
    int i = blockIdx.x * blockDim.x + threadIdx.x;
    if (i < N_NODES * OUT_C) {
        out[i] = g_inv[i >> 6] * out[i] + __ldg(b2 + (i & 63));
    }
}

// ---------------------------------------------------------------------------
extern "C" void kernel_launch(void* const* d_in, const int* in_sizes, int n_in,
                              void* d_out, int out_size) {
    const float* x  = (const float*)d_in[0];
    const void*  ei = d_in[1];                  // int64 or int32 (detected)
    const float* W1 = (const float*)d_in[2];
    const float* b1 = (const float*)d_in[3];
    const float* W2 = (const float*)d_in[4];
    const float* b2 = (const float*)d_in[5];
    float* out = (float*)d_out;

    k_initdeg<<<(N_NODES + 255) / 256, 256>>>();
    k_detect<<<16, 256>>>((const long long*)ei);
    k_count<<<(N_EDGES + 255) / 256, 256>>>(ei);
    k_inv<<<(N_NODES + 255) / 256, 256>>>();

    k_gemm1<<<(N_NODES + 127) / 128, 256>>>(x, W1);
    k_scatter1<<<(int)(((long long)N_EDGES * 32 + 255) / 256), 256>>>(ei);

    k_gemm2<<<(N_NODES + 127) / 128, 256>>>(W2, b1, out);
    k_scatter2<<<(int)(((long long)N_EDGES * 16 + 255) / 256), 256>>>(ei, out);

    k_final<<<(N_NODES * OUT_C + 255) / 256, 256>>>(out, b2);
}

// round 2
// speedup vs baseline: 1.6986x; 1.6986x over previous
#include <cuda_runtime.h>
#include <cuda_bf16.h>

#define N_NODES 100000
#define N_EDGES 1600000
#define IN_C    128
#define HID_C   128
#define OUT_C   64
#define N_PAD   100352          // 392*256 >= N_NODES+1

// Scratch (no allocations allowed -> __device__ globals)
__device__ float g_hs1 [(size_t)N_NODES * HID_C];  // inv[s]*h1[s]
__device__ float g_a1  [(size_t)N_NODES * HID_C];  // relu(inv*(agg)+b1)  (GEMM2 input)
__device__ float g_hs2 [(size_t)N_NODES * OUT_C];  // inv[s]*h2[s]
__device__ int   g_deg [N_NODES];                  // edge-degree (excl self loop)
__device__ float g_inv [N_NODES];
__device__ int   g_ro  [N_PAD];                    // CSR row offsets (by dst)
__device__ int   g_cur [N_PAD];                    // fill cursors
__device__ int   g_csr [N_EDGES];                  // src indices grouped by dst
__device__ int   g_bsum[512];
__device__ int   g_boff[512];
__device__ int   g_is32;

// ---------------------------------------------------------------------------
__device__ __forceinline__ int edge_val(const void* ei, int is32, long long idx) {
    if (is32) return ((const int*)ei)[idx];
    return (int)(((const long long*)ei)[idx]);
}

// ---------------------------------------------------------------------------
// setup
// ---------------------------------------------------------------------------
__global__ void k_init() {
    int i = blockIdx.x * blockDim.x + threadIdx.x;
    if (i < N_NODES) g_deg[i] = 0;
    if (i == 0) g_is32 = 0;
}

__global__ void k_detect(const long long* __restrict__ ei) {
    int i = blockIdx.x * blockDim.x + threadIdx.x;
    if (i < 4096) {
        long long v = ei[i];
        if (v < 0 || v >= N_NODES) g_is32 = 1;
    }
}

__global__ void k_count(const void* __restrict__ ei) {
    int e = blockIdx.x * blockDim.x + threadIdx.x;
    if (e < N_EDGES) {
        int d = edge_val(ei, g_is32, (long long)N_EDGES + e);
        atomicAdd(&g_deg[d], 1);
    }
}

__global__ void k_inv() {
    int i = blockIdx.x * blockDim.x + threadIdx.x;
    if (i < N_NODES) g_inv[i] = rsqrtf((float)(g_deg[i] + 1));   // +1 self loop
}

// ---- 3-step exclusive scan of g_deg into g_ro --------------------------------
__global__ void k_scan1() {
    __shared__ int sh[256];
    int t = threadIdx.x;
    int i = blockIdx.x * 256 + t;
    int v = (i < N_NODES) ? g_deg[i] : 0;
    sh[t] = v; __syncthreads();
    #pragma unroll
    for (int off = 1; off < 256; off <<= 1) {
        int add = (t >= off) ? sh[t - off] : 0;
        __syncthreads();
        sh[t] += add;
        __syncthreads();
    }
    g_ro[i] = sh[t] - v;                 // exclusive
    if (t == 255) g_bsum[blockIdx.x] = sh[255];
}

__global__ void k_scan2(int nblocks) {
    __shared__ int sh[512];
    int t = threadIdx.x;
    int v = (t < nblocks) ? g_bsum[t] : 0;
    sh[t] = v; __syncthreads();
    #pragma unroll
    for (int off = 1; off < 512; off <<= 1) {
        int add = (t >= off) ? sh[t - off] : 0;
        __syncthreads();
        sh[t] += add;
        __syncthreads();
    }
    g_boff[t] = sh[t] - v;               // exclusive
}

__global__ void k_scan3() {
    int i = blockIdx.x * 256 + threadIdx.x;
    int v = g_ro[i] + g_boff[blockIdx.x];
    g_ro[i]  = v;
    g_cur[i] = v;
}

__global__ void k_fill(const void* __restrict__ ei) {
    int e = blockIdx.x * blockDim.x + threadIdx.x;
    if (e < N_EDGES) {
        int is32 = g_is32;
        int s = edge_val(ei, is32, e);
        int d = edge_val(ei, is32, (long long)N_EDGES + e);
        int pos = atomicAdd(&g_cur[d], 1);
        g_csr[pos] = s;
    }
}

// ---------------------------------------------------------------------------
// GEMM1: hs1 = inv[row] * (X @ W1)
// ---------------------------------------------------------------------------
__global__ __launch_bounds__(256) void k_gemm1(const float* __restrict__ X,
                                               const float* __restrict__ W) {
    __shared__ float As[128][33];
    __shared__ float Bs[32][128];
    const int tid = threadIdx.x;
    const int tx = tid & 15, ty = tid >> 4;
    const int blockRow = blockIdx.x * 128;
    float acc[8][8];
    #pragma unroll
    for (int i = 0; i < 8; i++)
        #pragma unroll
        for (int j = 0; j < 8; j++) acc[i][j] = 0.f;

    for (int kc = 0; kc < IN_C; kc += 32) {
        #pragma unroll
        for (int it = 0; it < 4; it++) {
            int idx = tid + it * 256;
            int r = idx >> 3, c4 = idx & 7;
            int row = blockRow + r;
            float4 v = make_float4(0.f, 0.f, 0.f, 0.f);
            if (row < N_NODES)
                v = *(const float4*)(X + (size_t)row * IN_C + kc + c4 * 4);
            As[r][c4 * 4 + 0] = v.x; As[r][c4 * 4 + 1] = v.y;
            As[r][c4 * 4 + 2] = v.z; As[r][c4 * 4 + 3] = v.w;
        }
        #pragma unroll
        for (int it = 0; it < 4; it++) {
            int idx = tid + it * 256;
            int r = idx >> 5, c4 = idx & 31;
            *(float4*)&Bs[r][c4 * 4] =
                *(const float4*)(W + (size_t)(kc + r) * HID_C + c4 * 4);
        }
        __syncthreads();
        #pragma unroll
        for (int k = 0; k < 32; k++) {
            float a[8], b[8];
            #pragma unroll
            for (int i = 0; i < 8; i++) a[i] = As[ty + 16 * i][k];
            #pragma unroll
            for (int j = 0; j < 8; j++) b[j] = Bs[k][tx + 16 * j];
            #pragma unroll
            for (int i = 0; i < 8; i++)
                #pragma unroll
                for (int j = 0; j < 8; j++) acc[i][j] += a[i] * b[j];
        }
        __syncthreads();
    }

    #pragma unroll
    for (int i = 0; i < 8; i++) {
        int row = blockRow + ty + 16 * i;
        if (row < N_NODES) {
            float iv = g_inv[row];
            #pragma unroll
            for (int j = 0; j < 8; j++)
                g_hs1[(size_t)row * HID_C + tx + 16 * j] = iv * acc[i][j];
        }
    }
}

// ---------------------------------------------------------------------------
// agg1: warp per node. a1[d] = relu(inv[d]*(hs1[d] + sum_src hs1[src]) + b1)
// ---------------------------------------------------------------------------
__global__ __launch_bounds__(256) void k_agg1(const float* __restrict__ b1) {
    int node = blockIdx.x * 8 + (threadIdx.x >> 5);
    if (node >= N_NODES) return;
    int lane = threadIdx.x & 31;
    const float4* base = (const float4*)g_hs1;

    float4 acc = __ldg(&base[(size_t)node * 32 + lane]);   // self loop
    int j  = g_ro[node];
    int je = g_ro[node + 1];
    for (; j + 1 < je; j += 2) {
        int sa = __ldg(&g_csr[j]);
        int sb = __ldg(&g_csr[j + 1]);
        float4 va = __ldg(&base[(size_t)sa * 32 + lane]);
        float4 vb = __ldg(&base[(size_t)sb * 32 + lane]);
        acc.x += va.x + vb.x; acc.y += va.y + vb.y;
        acc.z += va.z + vb.z; acc.w += va.w + vb.w;
    }
    if (j < je) {
        int sa = __ldg(&g_csr[j]);
        float4 va = __ldg(&base[(size_t)sa * 32 + lane]);
        acc.x += va.x; acc.y += va.y; acc.z += va.z; acc.w += va.w;
    }
    float iv = g_inv[node];
    float4 bb = __ldg((const float4*)b1 + lane);
    float4 r;
    r.x = fmaxf(iv * acc.x + bb.x, 0.f);
    r.y = fmaxf(iv * acc.y + bb.y, 0.f);
    r.z = fmaxf(iv * acc.z + bb.z, 0.f);
    r.w = fmaxf(iv * acc.w + bb.w, 0.f);
    ((float4*)g_a1)[(size_t)node * 32 + lane] = r;
}

// ---------------------------------------------------------------------------
// GEMM2: hs2 = inv[row] * (a1 @ W2)
// ---------------------------------------------------------------------------
__global__ __launch_bounds__(256) void k_gemm2(const float* __restrict__ W2) {
    __shared__ float As[128][33];
    __shared__ float Bs[32][64];
    const int tid = threadIdx.x;
    const int tx = tid & 15, ty = tid >> 4;
    const int blockRow = blockIdx.x * 128;
    float acc[8][4];
    #pragma unroll
    for (int i = 0; i < 8; i++)
        #pragma unroll
        for (int j = 0; j < 4; j++) acc[i][j] = 0.f;

    for (int kc = 0; kc < HID_C; kc += 32) {
        #pragma unroll
        for (int it = 0; it < 4; it++) {
            int idx = tid + it * 256;
            int r = idx >> 3, c4 = idx & 7;
            int row = blockRow + r;
            float4 v = make_float4(0.f, 0.f, 0.f, 0.f);
            if (row < N_NODES)
                v = *(const float4*)(g_a1 + (size_t)row * HID_C + kc + c4 * 4);
            As[r][c4 * 4 + 0] = v.x; As[r][c4 * 4 + 1] = v.y;
            As[r][c4 * 4 + 2] = v.z; As[r][c4 * 4 + 3] = v.w;
        }
        #pragma unroll
        for (int it = 0; it < 2; it++) {
            int idx = tid + it * 256;
            int r = idx >> 4, c4 = idx & 15;
            *(float4*)&Bs[r][c4 * 4] =
                *(const float4*)(W2 + (size_t)(kc + r) * OUT_C + c4 * 4);
        }
        __syncthreads();
        #pragma unroll
        for (int k = 0; k < 32; k++) {
            float a[8], b[4];
            #pragma unroll
            for (int i = 0; i < 8; i++) a[i] = As[ty + 16 * i][k];
            #pragma unroll
            for (int j = 0; j < 4; j++) b[j] = Bs[k][tx + 16 * j];
            #pragma unroll
            for (int i = 0; i < 8; i++)
                #pragma unroll
                for (int j = 0; j < 4; j++) acc[i][j] += a[i] * b[j];
        }
        __syncthreads();
    }

    #pragma unroll
    for (int i = 0; i < 8; i++) {
        int row = blockRow + ty + 16 * i;
        if (row < N_NODES) {
            float iv = g_inv[row];
            #pragma unroll
            for (int j = 0; j < 4; j++)
                g_hs2[(size_t)row * OUT_C + tx + 16 * j] = iv * acc[i][j];
        }
    }
}

// ---------------------------------------------------------------------------
// agg2: warp per node (float2/lane). out[d] = inv[d]*(hs2[d]+sum hs2[src]) + b2
// ---------------------------------------------------------------------------
__global__ __launch_bounds__(256) void k_agg2(float* __restrict__ out,
                                              const float* __restrict__ b2) {
    int node = blockIdx.x * 8 + (threadIdx.x >> 5);
    if (node >= N_NODES) return;
    int lane = threadIdx.x & 31;
    const float2* base = (const float2*)g_hs2;

    float2 acc = __ldg(&base[(size_t)node * 32 + lane]);   // self loop
    int j  = g_ro[node];
    int je = g_ro[node + 1];
    for (; j + 1 < je; j += 2) {
        int sa = __ldg(&g_csr[j]);
        int sb = __ldg(&g_csr[j + 1]);
        float2 va = __ldg(&base[(size_t)sa * 32 + lane]);
        float2 vb = __ldg(&base[(size_t)sb * 32 + lane]);
        acc.x += va.x + vb.x; acc.y += va.y + vb.y;
    }
    if (j < je) {
        int sa = __ldg(&g_csr[j]);
        float2 va = __ldg(&base[(size_t)sa * 32 + lane]);
        acc.x += va.x; acc.y += va.y;
    }
    float iv = g_inv[node];
    float2 bb = __ldg((const float2*)b2 + lane);
    float2 r;
    r.x = iv * acc.x + bb.x;
    r.y = iv * acc.y + bb.y;
    ((float2*)out)[(size_t)node * 32 + lane] = r;
}

// ---------------------------------------------------------------------------
extern "C" void kernel_launch(void* const* d_in, const int* in_sizes, int n_in,
                              void* d_out, int out_size) {
    const float* x  = (const float*)d_in[0];
    const void*  ei = d_in[1];
    const float* W1 = (const float*)d_in[2];
    const float* b1 = (const float*)d_in[3];
    const float* W2 = (const float*)d_in[4];
    const float* b2 = (const float*)d_in[5];
    float* out = (float*)d_out;

    const int SCAN_BLOCKS = N_PAD / 256;   // 392

    k_init  <<<(N_NODES + 255) / 256, 256>>>();
    k_detect<<<16, 256>>>((const long long*)ei);
    k_count <<<(N_EDGES + 255) / 256, 256>>>(ei);
    k_inv   <<<(N_NODES + 255) / 256, 256>>>();
    k_scan1 <<<SCAN_BLOCKS, 256>>>();
    k_scan2 <<<1, 512>>>(SCAN_BLOCKS);
    k_scan3 <<<SCAN_BLOCKS, 256>>>();
    k_fill  <<<(N_EDGES + 255) / 256, 256>>>(ei);

    k_gemm1 <<<(N_NODES + 127) / 128, 256>>>(x, W1);
    k_agg1  <<<(N_NODES + 7) / 8, 256>>>(b1);
    k_gemm2 <<<(N_NODES + 127) / 128, 256>>>(W2);
    k_agg2  <<<(N_NODES + 7) / 8, 256>>>(out, b2);
}

// round 4
// speedup vs baseline: 1.8264x; 1.0753x over previous
#include <cuda_runtime.h>
#include <cuda_bf16.h>
#include <cstdint>

#define N_NODES 100000
#define N_EDGES 1600000
#define IN_C    128
#define HID_C   128
#define OUT_C   64
#define N_PAD   100352          // 392*256 >= N_NODES+1

// Scratch (no allocations allowed -> __device__ globals)
__device__ float g_hs1 [(size_t)N_NODES * HID_C];  // inv[s]*h1[s]
__device__ float g_a1  [(size_t)N_NODES * HID_C];  // relu(inv*(agg)+b1)
__device__ float g_hs2 [(size_t)N_NODES * OUT_C];  // inv[s]*h2[s]
__device__ int   g_deg [N_NODES];
__device__ float g_inv [N_NODES];
__device__ int   g_ro  [N_PAD];
__device__ int   g_cur [N_PAD];
__device__ int   g_csr [N_EDGES];
__device__ int   g_bsum[512];
__device__ int   g_boff[512];
__device__ int   g_is32;

// ---------------------------------------------------------------------------
// helpers
// ---------------------------------------------------------------------------
__device__ __forceinline__ uint32_t smem_u32(const void* p) {
    uint32_t a;
    asm("{ .reg .u64 t; cvta.to.shared.u64 t, %1; cvt.u32.u64 %0, t; }" : "=r"(a) : "l"(p));
    return a;
}
__device__ __forceinline__ void ldm_x4(uint32_t* r, uint32_t addr) {
    asm volatile("ldmatrix.sync.aligned.m8n8.x4.shared.b16 {%0,%1,%2,%3}, [%4];"
                 : "=r"(r[0]), "=r"(r[1]), "=r"(r[2]), "=r"(r[3]) : "r"(addr));
}
__device__ __forceinline__ void ldm_x4t(uint32_t* r, uint32_t addr) {
    asm volatile("ldmatrix.sync.aligned.m8n8.x4.trans.shared.b16 {%0,%1,%2,%3}, [%4];"
                 : "=r"(r[0]), "=r"(r[1]), "=r"(r[2]), "=r"(r[3]) : "r"(addr));
}
__device__ __forceinline__ void mma_bf16(float* c, const uint32_t* a, const uint32_t* b) {
    asm volatile("mma.sync.aligned.m16n8k16.row.col.f32.bf16.bf16.f32 "
                 "{%0,%1,%2,%3}, {%4,%5,%6,%7}, {%8,%9}, {%0,%1,%2,%3};"
                 : "+f"(c[0]), "+f"(c[1]), "+f"(c[2]), "+f"(c[3])
                 : "r"(a[0]), "r"(a[1]), "r"(a[2]), "r"(a[3]), "r"(b[0]), "r"(b[1]));
}
__device__ __forceinline__ uint32_t pack_bf16(float a, float b, float& ra, float& rb) {
    __nv_bfloat16 ha = __float2bfloat16(a), hb = __float2bfloat16(b);
    ra = a - __bfloat162float(ha);
    rb = b - __bfloat162float(hb);
    return (uint32_t)__bfloat16_as_ushort(ha) | ((uint32_t)__bfloat16_as_ushort(hb) << 16);
}
__device__ __forceinline__ uint32_t pack_bf16_lo(float a, float b) {
    return (uint32_t)__bfloat16_as_ushort(__float2bfloat16(a))
         | ((uint32_t)__bfloat16_as_ushort(__float2bfloat16(b)) << 16);
}
__device__ __forceinline__ int edge_val(const void* ei, int is32, long long idx) {
    if (is32) return ((const int*)ei)[idx];
    return (int)(((const long long*)ei)[idx]);
}

// ---------------------------------------------------------------------------
// setup
// ---------------------------------------------------------------------------
__global__ void k_init() {
    int i = blockIdx.x * blockDim.x + threadIdx.x;
    if (i < N_NODES) g_deg[i] = 0;
    if (i == 0) g_is32 = 0;
}
__global__ void k_detect(const long long* __restrict__ ei) {
    int i = blockIdx.x * blockDim.x + threadIdx.x;
    if (i < 4096) {
        long long v = ei[i];
        if (v < 0 || v >= N_NODES) g_is32 = 1;
    }
}
__global__ void k_count(const void* __restrict__ ei) {
    int e = blockIdx.x * blockDim.x + threadIdx.x;
    if (e < N_EDGES) {
        int d = edge_val(ei, g_is32, (long long)N_EDGES + e);
        atomicAdd(&g_deg[d], 1);
    }
}
__global__ void k_inv() {
    int i = blockIdx.x * blockDim.x + threadIdx.x;
    if (i < N_NODES) g_inv[i] = rsqrtf((float)(g_deg[i] + 1));
}
__global__ void k_scan1() {
    __shared__ int sh[256];
    int t = threadIdx.x;
    int i = blockIdx.x * 256 + t;
    int v = (i < N_NODES) ? g_deg[i] : 0;
    sh[t] = v; __syncthreads();
    #pragma unroll
    for (int off = 1; off < 256; off <<= 1) {
        int add = (t >= off) ? sh[t - off] : 0;
        __syncthreads();
        sh[t] += add;
        __syncthreads();
    }
    g_ro[i] = sh[t] - v;
    if (t == 255) g_bsum[blockIdx.x] = sh[255];
}
__global__ void k_scan2(int nblocks) {
    __shared__ int sh[512];
    int t = threadIdx.x;
    int v = (t < nblocks) ? g_bsum[t] : 0;
    sh[t] = v; __syncthreads();
    #pragma unroll
    for (int off = 1; off < 512; off <<= 1) {
        int add = (t >= off) ? sh[t - off] : 0;
        __syncthreads();
        sh[t] += add;
        __syncthreads();
    }
    g_boff[t] = sh[t] - v;
}
__global__ void k_scan3() {
    int i = blockIdx.x * 256 + threadIdx.x;
    int v = g_ro[i] + g_boff[blockIdx.x];
    g_ro[i]  = v;
    g_cur[i] = v;
}
__global__ void k_fill(const void* __restrict__ ei) {
    int e = blockIdx.x * blockDim.x + threadIdx.x;
    if (e < N_EDGES) {
        int is32 = g_is32;
        int s = edge_val(ei, is32, e);
        int d = edge_val(ei, is32, (long long)N_EDGES + e);
        int pos = atomicAdd(&g_cur[d], 1);
        g_csr[pos] = s;
    }
}

// ---------------------------------------------------------------------------
// Warp-MMA split-bf16 GEMM: Out[row,0:NC] = inv[row] * (A[row,0:128] @ W[0:128,0:NC])
// 3 passes: Ahi*Bhi + Ahi*Blo + Alo*Bhi (fp32 accumulate).
// A smem: [128][136] bf16 (K-major, pad keeps ldmatrix conflict-free).
// B smem: [128][NC+8] bf16 (row-major = coalesced fill from W; .trans ldmatrix).
// 8 warps: 4 (M) x 2 (N); warp tile 32 x NC/2.
// ---------------------------------------------------------------------------
template<int NC>
__global__ __launch_bounds__(256, 1) void k_mgemm(const float* __restrict__ A,
                                                  const float* __restrict__ W,
                                                  float* __restrict__ Out) {
    constexpr int WN   = NC / 2;        // warp N extent
    constexpr int NT   = WN / 8;        // 8-wide n-tiles per warp
    constexpr int AST  = 136;           // A row stride (elems)
    constexpr int BST  = NC + 8;        // B row stride (elems)
    constexpr int A_HI = 0;
    constexpr int A_LO = 128 * AST * 2;
    constexpr int B_HI = 2 * 128 * AST * 2;
    constexpr int B_LO = B_HI + 128 * BST * 2;

    extern __shared__ char smem[];
    const uint32_t sb = smem_u32(smem);
    const int tid = threadIdx.x, wid = tid >> 5, lane = tid & 31;
    const int blockRow = blockIdx.x * 128;

    // ---- fill A (hi/lo bf16) ----
    for (int idx = tid; idx < 128 * 64; idx += 256) {
        int r = idx >> 6, k2 = (idx & 63) << 1;
        int row = blockRow + r;
        float a0 = 0.f, a1 = 0.f;
        if (row < N_NODES) {
            float2 v = *(const float2*)(A + (size_t)row * 128 + k2);
            a0 = v.x; a1 = v.y;
        }
        float l0, l1;
        uint32_t hi = pack_bf16(a0, a1, l0, l1);
        uint32_t lo = pack_bf16_lo(l0, l1);
        uint32_t off = (uint32_t)(r * AST + k2) * 2;
        *(uint32_t*)(smem + A_HI + off) = hi;
        *(uint32_t*)(smem + A_LO + off) = lo;
    }
    // ---- fill B (hi/lo), coalesced from W[k][n] ----
    for (int idx = tid; idx < 128 * (NC / 2); idx += 256) {
        int k = idx / (NC / 2), n2 = (idx % (NC / 2)) << 1;
        float2 w = *(const float2*)(W + (size_t)k * NC + n2);
        float l0, l1;
        uint32_t hi = pack_bf16(w.x, w.y, l0, l1);
        uint32_t lo = pack_bf16_lo(l0, l1);
        uint32_t off = (uint32_t)(k * BST + n2) * 2;
        *(uint32_t*)(smem + B_HI + off) = hi;
        *(uint32_t*)(smem + B_LO + off) = lo;
    }
    __syncthreads();

    const int wm = (wid & 3) * 32;
    const int wn = (wid >> 2) * WN;

    float acc[2][NT][4];
    #pragma unroll
    for (int mt = 0; mt < 2; mt++)
        #pragma unroll
        for (int nt = 0; nt < NT; nt++)
            #pragma unroll
            for (int i = 0; i < 4; i++) acc[mt][nt][i] = 0.f;

    // ldmatrix lane address components
    const int laA = lane & 15, lbA = lane >> 4;                 // A: row-in-tile, k-half
    const int rB = (((lane >> 3) & 1) << 3) + (lane & 7);       // B: k-row offset
    const int cB = (lane >> 4) << 3;                            // B: n offset

    #pragma unroll
    for (int ks = 0; ks < 8; ks++) {
        const int k0 = ks * 16;
        uint32_t a_hi[2][4], a_lo[2][4], bh[NT][2], bl[NT][2];
        #pragma unroll
        for (int mt = 0; mt < 2; mt++) {
            uint32_t addr = sb + A_HI + (uint32_t)((wm + mt * 16 + laA) * AST + k0 + lbA * 8) * 2;
            ldm_x4(a_hi[mt], addr);
            ldm_x4(a_lo[mt], addr + (A_LO - A_HI));
        }
        #pragma unroll
        for (int nt2 = 0; nt2 < NT / 2; nt2++) {
            uint32_t addr = sb + B_HI + (uint32_t)((k0 + rB) * BST + wn + nt2 * 16 + cB) * 2;
            uint32_t t[4];
            ldm_x4t(t, addr);
            bh[2 * nt2][0] = t[0]; bh[2 * nt2][1] = t[1];
            bh[2 * nt2 + 1][0] = t[2]; bh[2 * nt2 + 1][1] = t[3];
            ldm_x4t(t, addr + (B_LO - B_HI));
            bl[2 * nt2][0] = t[0]; bl[2 * nt2][1] = t[1];
            bl[2 * nt2 + 1][0] = t[2]; bl[2 * nt2 + 1][1] = t[3];
        }
        #pragma unroll
        for (int mt = 0; mt < 2; mt++)
            #pragma unroll
            for (int nt = 0; nt < NT; nt++) {
                mma_bf16(acc[mt][nt], a_hi[mt], bh[nt]);
                mma_bf16(acc[mt][nt], a_hi[mt], bl[nt]);
                mma_bf16(acc[mt][nt], a_lo[mt], bh[nt]);
            }
    }

    // ---- epilogue: scale by inv[row], direct float2 stores ----
    #pragma unroll
    for (int mt = 0; mt < 2; mt++) {
        int row0 = blockRow + wm + mt * 16 + (lane >> 2);
        int row1 = row0 + 8;
        float iv0 = (row0 < N_NODES) ? g_inv[row0] : 0.f;
        float iv1 = (row1 < N_NODES) ? g_inv[row1] : 0.f;
        #pragma unroll
        for (int nt = 0; nt < NT; nt++) {
            int col = wn + nt * 8 + (lane & 3) * 2;
            if (row0 < N_NODES) {
                float2 v; v.x = iv0 * acc[mt][nt][0]; v.y = iv0 * acc[mt][nt][1];
                *(float2*)(Out + (size_t)row0 * NC + col) = v;
            }
            if (row1 < N_NODES) {
                float2 v; v.x = iv1 * acc[mt][nt][2]; v.y = iv1 * acc[mt][nt][3];
                *(float2*)(Out + (size_t)row1 * NC + col) = v;
            }
        }
    }
}

// ---------------------------------------------------------------------------
// agg1: warp per node. a1[d] = relu(inv[d]*(hs1[d] + sum_src hs1[src]) + b1)
// ---------------------------------------------------------------------------
__global__ __launch_bounds__(256) void k_agg1(const float* __restrict__ b1) {
    int node = blockIdx.x * 8 + (threadIdx.x >> 5);
    if (node >= N_NODES) return;
    int lane = threadIdx.x & 31;
    const float4* base = (const float4*)g_hs1;

    float4 acc = __ldg(&base[(size_t)node * 32 + lane]);   // self loop
    int j  = g_ro[node];
    int je = g_ro[node + 1];
    for (; j + 1 < je; j += 2) {
        int sa = __ldg(&g_csr[j]);
        int sb2 = __ldg(&g_csr[j + 1]);
        float4 va = __ldg(&base[(size_t)sa * 32 + lane]);
        float4 vb = __ldg(&base[(size_t)sb2 * 32 + lane]);
        acc.x += va.x + vb.x; acc.y += va.y + vb.y;
        acc.z += va.z + vb.z; acc.w += va.w + vb.w;
    }
    if (j < je) {
        int sa = __ldg(&g_csr[j]);
        float4 va = __ldg(&base[(size_t)sa * 32 + lane]);
        acc.x += va.x; acc.y += va.y; acc.z += va.z; acc.w += va.w;
    }
    float iv = g_inv[node];
    float4 bb = __ldg((const float4*)b1 + lane);
    float4 r;
    r.x = fmaxf(iv * acc.x + bb.x, 0.f);
    r.y = fmaxf(iv * acc.y + bb.y, 0.f);
    r.z = fmaxf(iv * acc.z + bb.z, 0.f);
    r.w = fmaxf(iv * acc.w + bb.w, 0.f);
    ((float4*)g_a1)[(size_t)node * 32 + lane] = r;
}

// ---------------------------------------------------------------------------
// agg2: warp per node (float2/lane). out[d] = inv[d]*(hs2[d]+sum hs2[src]) + b2
// ---------------------------------------------------------------------------
__global__ __launch_bounds__(256) void k_agg2(float* __restrict__ out,
                                              const float* __restrict__ b2) {
    int node = blockIdx.x * 8 + (threadIdx.x >> 5);
    if (node >= N_NODES) return;
    int lane = threadIdx.x & 31;
    const float2* base = (const float2*)g_hs2;

    float2 acc = __ldg(&base[(size_t)node * 32 + lane]);   // self loop
    int j  = g_ro[node];
    int je = g_ro[node + 1];
    for (; j + 1 < je; j += 2) {
        int sa = __ldg(&g_csr[j]);
        int sb2 = __ldg(&g_csr[j + 1]);
        float2 va = __ldg(&base[(size_t)sa * 32 + lane]);
        float2 vb = __ldg(&base[(size_t)sb2 * 32 + lane]);
        acc.x += va.x + vb.x; acc.y += va.y + vb.y;
    }
    if (j < je) {
        int sa = __ldg(&g_csr[j]);
        float2 va = __ldg(&base[(size_t)sa * 32 + lane]);
        acc.x += va.x; acc.y += va.y;
    }
    float iv = g_inv[node];
    float2 bb = __ldg((const float2*)b2 + lane);
    float2 r;
    r.x = iv * acc.x + bb.x;
    r.y = iv * acc.y + bb.y;
    ((float2*)out)[(size_t)node * 32 + lane] = r;
}

// ---------------------------------------------------------------------------
extern "C" void kernel_launch(void* const* d_in, const int* in_sizes, int n_in,
                              void* d_out, int out_size) {
    const float* x  = (const float*)d_in[0];
    const void*  ei = d_in[1];
    const float* W1 = (const float*)d_in[2];
    const float* b1 = (const float*)d_in[3];
    const float* W2 = (const float*)d_in[4];
    const float* b2 = (const float*)d_in[5];
    float* out = (float*)d_out;

    const int SCAN_BLOCKS = N_PAD / 256;   // 392
    const int SMEM1 = 2 * 128 * 136 * 2 + 2 * 128 * (128 + 8) * 2;  // 139264
    const int SMEM2 = 2 * 128 * 136 * 2 + 2 * 128 * (64 + 8) * 2;   // 106496

    cudaFuncSetAttribute(k_mgemm<128>, cudaFuncAttributeMaxDynamicSharedMemorySize, SMEM1);
    cudaFuncSetAttribute(k_mgemm<64>,  cudaFuncAttributeMaxDynamicSharedMemorySize, SMEM2);

    float* hs1 = nullptr; cudaGetSymbolAddress((void**)&hs1, g_hs1);
    float* a1  = nullptr; cudaGetSymbolAddress((void**)&a1,  g_a1);
    float* hs2 = nullptr; cudaGetSymbolAddress((void**)&hs2, g_hs2);

    k_init  <<<(N_NODES + 255) / 256, 256>>>();
    k_detect<<<16, 256>>>((const long long*)ei);
    k_count <<<(N_EDGES + 255) / 256, 256>>>(ei);
    k_inv   <<<(N_NODES + 255) / 256, 256>>>();
    k_scan1 <<<SCAN_BLOCKS, 256>>>();
    k_scan2 <<<1, 512>>>(SCAN_BLOCKS);
    k_scan3 <<<SCAN_BLOCKS, 256>>>();
    k_fill  <<<(N_EDGES + 255) / 256, 256>>>(ei);

    k_mgemm<128><<<(N_NODES + 127) / 128, 256, SMEM1>>>(x, W1, hs1);
    k_agg1  <<<(N_NODES + 7) / 8, 256>>>(b1);
    k_mgemm<64> <<<(N_NODES + 127) / 128, 256, SMEM2>>>(a1, W2, hs2);
    k_agg2  <<<(N_NODES + 7) / 8, 256>>>(out, b2);
}

// round 5
// speedup vs baseline: 1.9654x; 1.0761x over previous
#include <cuda_runtime.h>
#include <cuda_bf16.h>
#include <cuda_fp16.h>
#include <cstdint>

#define N_NODES 100000
#define N_EDGES 1600000
#define IN_C    128
#define HID_C   128
#define OUT_C   64
#define N_PAD   100352          // 392*256 >= N_NODES+1

// Scratch (no allocations allowed -> __device__ globals)
__device__ __half g_hs1h[(size_t)N_NODES * HID_C]; // fp16 inv[s]*h1[s] (gather src L1)
__device__ float  g_a1  [(size_t)N_NODES * HID_C]; // relu(inv*(agg)+b1) fp32 (GEMM2 in)
__device__ __half g_hs2h[(size_t)N_NODES * OUT_C]; // fp16 inv[s]*h2[s] (gather src L2)
__device__ int    g_deg [N_NODES];
__device__ float  g_inv [N_NODES];
__device__ int    g_ro  [N_PAD];
__device__ int    g_cur [N_PAD];
__device__ int    g_csr [N_EDGES];
__device__ int    g_bsum[512];
__device__ int    g_boff[512];
__device__ int    g_is32;

// ---------------------------------------------------------------------------
// helpers
// ---------------------------------------------------------------------------
__device__ __forceinline__ uint32_t smem_u32(const void* p) {
    uint32_t a;
    asm("{ .reg .u64 t; cvta.to.shared.u64 t, %1; cvt.u32.u64 %0, t; }" : "=r"(a) : "l"(p));
    return a;
}
__device__ __forceinline__ void ldm_x4(uint32_t* r, uint32_t addr) {
    asm volatile("ldmatrix.sync.aligned.m8n8.x4.shared.b16 {%0,%1,%2,%3}, [%4];"
                 : "=r"(r[0]), "=r"(r[1]), "=r"(r[2]), "=r"(r[3]) : "r"(addr));
}
__device__ __forceinline__ void ldm_x4t(uint32_t* r, uint32_t addr) {
    asm volatile("ldmatrix.sync.aligned.m8n8.x4.trans.shared.b16 {%0,%1,%2,%3}, [%4];"
                 : "=r"(r[0]), "=r"(r[1]), "=r"(r[2]), "=r"(r[3]) : "r"(addr));
}
__device__ __forceinline__ void mma_bf16(float* c, const uint32_t* a, const uint32_t* b) {
    asm volatile("mma.sync.aligned.m16n8k16.row.col.f32.bf16.bf16.f32 "
                 "{%0,%1,%2,%3}, {%4,%5,%6,%7}, {%8,%9}, {%0,%1,%2,%3};"
                 : "+f"(c[0]), "+f"(c[1]), "+f"(c[2]), "+f"(c[3])
                 : "r"(a[0]), "r"(a[1]), "r"(a[2]), "r"(a[3]), "r"(b[0]), "r"(b[1]));
}
__device__ __forceinline__ uint32_t pack_bf16(float a, float b, float& ra, float& rb) {
    __nv_bfloat16 ha = __float2bfloat16(a), hb = __float2bfloat16(b);
    ra = a - __bfloat162float(ha);
    rb = b - __bfloat162float(hb);
    return (uint32_t)__bfloat16_as_ushort(ha) | ((uint32_t)__bfloat16_as_ushort(hb) << 16);
}
__device__ __forceinline__ uint32_t pack_bf16_lo(float a, float b) {
    return (uint32_t)__bfloat16_as_ushort(__float2bfloat16(a))
         | ((uint32_t)__bfloat16_as_ushort(__float2bfloat16(b)) << 16);
}
__device__ __forceinline__ int edge_val(const void* ei, int is32, long long idx) {
    if (is32) return ((const int*)ei)[idx];
    return (int)(((const long long*)ei)[idx]);
}

// ---------------------------------------------------------------------------
// setup
// ---------------------------------------------------------------------------
__global__ void k_init() {
    int i = blockIdx.x * blockDim.x + threadIdx.x;
    if (i < N_NODES) g_deg[i] = 0;
    if (i == 0) g_is32 = 0;
}
__global__ void k_detect(const long long* __restrict__ ei) {
    int i = blockIdx.x * blockDim.x + threadIdx.x;
    if (i < 4096) {
        long long v = ei[i];
        if (v < 0 || v >= N_NODES) g_is32 = 1;
    }
}
__global__ void k_count(const void* __restrict__ ei) {
    int e = blockIdx.x * blockDim.x + threadIdx.x;
    if (e < N_EDGES) {
        int d = edge_val(ei, g_is32, (long long)N_EDGES + e);
        atomicAdd(&g_deg[d], 1);
    }
}
// scan1 also produces g_inv (deg incl. self loop)
__global__ void k_scan1() {
    __shared__ int sh[256];
    int t = threadIdx.x;
    int i = blockIdx.x * 256 + t;
    int v = (i < N_NODES) ? g_deg[i] : 0;
    if (i < N_NODES) g_inv[i] = rsqrtf((float)(v + 1));
    sh[t] = v; __syncthreads();
    #pragma unroll
    for (int off = 1; off < 256; off <<= 1) {
        int add = (t >= off) ? sh[t - off] : 0;
        __syncthreads();
        sh[t] += add;
        __syncthreads();
    }
    g_ro[i] = sh[t] - v;
    if (t == 255) g_bsum[blockIdx.x] = sh[255];
}
__global__ void k_scan2(int nblocks) {
    __shared__ int sh[512];
    int t = threadIdx.x;
    int v = (t < nblocks) ? g_bsum[t] : 0;
    sh[t] = v; __syncthreads();
    #pragma unroll
    for (int off = 1; off < 512; off <<= 1) {
        int add = (t >= off) ? sh[t - off] : 0;
        __syncthreads();
        sh[t] += add;
        __syncthreads();
    }
    g_boff[t] = sh[t] - v;
}
__global__ void k_scan3() {
    int i = blockIdx.x * 256 + threadIdx.x;
    int v = g_ro[i] + g_boff[blockIdx.x];
    g_ro[i]  = v;
    g_cur[i] = v;
}
__global__ void k_fill(const void* __restrict__ ei) {
    int e = blockIdx.x * blockDim.x + threadIdx.x;
    if (e < N_EDGES) {
        int is32 = g_is32;
        int s = edge_val(ei, is32, e);
        int d = edge_val(ei, is32, (long long)N_EDGES + e);
        int pos = atomicAdd(&g_cur[d], 1);
        g_csr[pos] = s;
    }
}

// ---------------------------------------------------------------------------
// Warp-MMA split-bf16 GEMM: Out[row,0:NC] = inv[row] * (A[row,0:128] @ W[0:128,0:NC])
// Out in fp16. 3 passes: Ahi*Bhi + Ahi*Blo + Alo*Bhi (fp32 accumulate).
// ---------------------------------------------------------------------------
template<int NC>
__global__ __launch_bounds__(256, 1) void k_mgemm(const float* __restrict__ A,
                                                  const float* __restrict__ W,
                                                  __half* __restrict__ Out) {
    constexpr int WN   = NC / 2;
    constexpr int NT   = WN / 8;
    constexpr int AST  = 136;
    constexpr int BST  = NC + 8;
    constexpr int A_HI = 0;
    constexpr int A_LO = 128 * AST * 2;
    constexpr int B_HI = 2 * 128 * AST * 2;
    constexpr int B_LO = B_HI + 128 * BST * 2;

    extern __shared__ char smem[];
    const uint32_t sb = smem_u32(smem);
    const int tid = threadIdx.x, wid = tid >> 5, lane = tid & 31;
    const int blockRow = blockIdx.x * 128;

    // ---- fill A (hi/lo bf16) ----
    for (int idx = tid; idx < 128 * 64; idx += 256) {
        int r = idx >> 6, k2 = (idx & 63) << 1;
        int row = blockRow + r;
        float a0 = 0.f, a1 = 0.f;
        if (row < N_NODES) {
            float2 v = *(const float2*)(A + (size_t)row * 128 + k2);
            a0 = v.x; a1 = v.y;
        }
        float l0, l1;
        uint32_t hi = pack_bf16(a0, a1, l0, l1);
        uint32_t lo = pack_bf16_lo(l0, l1);
        uint32_t off = (uint32_t)(r * AST + k2) * 2;
        *(uint32_t*)(smem + A_HI + off) = hi;
        *(uint32_t*)(smem + A_LO + off) = lo;
    }
    // ---- fill B (hi/lo), coalesced from W[k][n] ----
    for (int idx = tid; idx < 128 * (NC / 2); idx += 256) {
        int k = idx / (NC / 2), n2 = (idx % (NC / 2)) << 1;
        float2 w = *(const float2*)(W + (size_t)k * NC + n2);
        float l0, l1;
        uint32_t hi = pack_bf16(w.x, w.y, l0, l1);
        uint32_t lo = pack_bf16_lo(l0, l1);
        uint32_t off = (uint32_t)(k * BST + n2) * 2;
        *(uint32_t*)(smem + B_HI + off) = hi;
        *(uint32_t*)(smem + B_LO + off) = lo;
    }
    __syncthreads();

    const int wm = (wid & 3) * 32;
    const int wn = (wid >> 2) * WN;

    float acc[2][NT][4];
    #pragma unroll
    for (int mt = 0; mt < 2; mt++)
        #pragma unroll
        for (int nt = 0; nt < NT; nt++)
            #pragma unroll
            for (int i = 0; i < 4; i++) acc[mt][nt][i] = 0.f;

    const int laA = lane & 15, lbA = lane >> 4;
    const int rB = (((lane >> 3) & 1) << 3) + (lane & 7);
    const int cB = (lane >> 4) << 3;

    #pragma unroll
    for (int ks = 0; ks < 8; ks++) {
        const int k0 = ks * 16;
        uint32_t a_hi[2][4], a_lo[2][4], bh[NT][2], bl[NT][2];
        #pragma unroll
        for (int mt = 0; mt < 2; mt++) {
            uint32_t addr = sb + A_HI + (uint32_t)((wm + mt * 16 + laA) * AST + k0 + lbA * 8) * 2;
            ldm_x4(a_hi[mt], addr);
            ldm_x4(a_lo[mt], addr + (A_LO - A_HI));
        }
        #pragma unroll
        for (int nt2 = 0; nt2 < NT / 2; nt2++) {
            uint32_t addr = sb + B_HI + (uint32_t)((k0 + rB) * BST + wn + nt2 * 16 + cB) * 2;
            uint32_t t[4];
            ldm_x4t(t, addr);
            bh[2 * nt2][0] = t[0]; bh[2 * nt2][1] = t[1];
            bh[2 * nt2 + 1][0] = t[2]; bh[2 * nt2 + 1][1] = t[3];
            ldm_x4t(t, addr + (B_LO - B_HI));
            bl[2 * nt2][0] = t[0]; bl[2 * nt2][1] = t[1];
            bl[2 * nt2 + 1][0] = t[2]; bl[2 * nt2 + 1][1] = t[3];
        }
        #pragma unroll
        for (int mt = 0; mt < 2; mt++)
            #pragma unroll
            for (int nt = 0; nt < NT; nt++) {
                mma_bf16(acc[mt][nt], a_hi[mt], bh[nt]);
                mma_bf16(acc[mt][nt], a_hi[mt], bl[nt]);
                mma_bf16(acc[mt][nt], a_lo[mt], bh[nt]);
            }
    }

    // ---- epilogue: scale by inv[row], half2 stores ----
    #pragma unroll
    for (int mt = 0; mt < 2; mt++) {
        int row0 = blockRow + wm + mt * 16 + (lane >> 2);
        int row1 = row0 + 8;
        float iv0 = (row0 < N_NODES) ? g_inv[row0] : 0.f;
        float iv1 = (row1 < N_NODES) ? g_inv[row1] : 0.f;
        #pragma unroll
        for (int nt = 0; nt < NT; nt++) {
            int col = wn + nt * 8 + (lane & 3) * 2;
            if (row0 < N_NODES) {
                __half2 h = __floats2half2_rn(iv0 * acc[mt][nt][0], iv0 * acc[mt][nt][1]);
                *(__half2*)(Out + (size_t)row0 * NC + col) = h;
            }
            if (row1 < N_NODES) {
                __half2 h = __floats2half2_rn(iv1 * acc[mt][nt][2], iv1 * acc[mt][nt][3]);
                *(__half2*)(Out + (size_t)row1 * NC + col) = h;
            }
        }
    }
}

// ---------------------------------------------------------------------------
// agg1: warp per node, fp16 gather (uint2 = 4 halves/lane), fp32 accumulate.
// a1[d] = relu(inv[d]*(hs1[d] + sum_src hs1[src]) + b1)   (a1 fp32)
// ---------------------------------------------------------------------------
__global__ __launch_bounds__(256) void k_agg1(const float* __restrict__ b1) {
    int node = blockIdx.x * 8 + (threadIdx.x >> 5);
    if (node >= N_NODES) return;
    int lane = threadIdx.x & 31;
    const uint2* base = (const uint2*)g_hs1h;   // 4 halves per lane

    uint2 sv = __ldg(&base[(size_t)node * 32 + lane]);   // self loop
    float2 p0 = __half22float2(*(__half2*)&sv.x);
    float2 p1 = __half22float2(*(__half2*)&sv.y);
    float ax = p0.x, ay = p0.y, az = p1.x, aw = p1.y;

    int j  = g_ro[node];
    int je = g_ro[node + 1];
    for (; j + 1 < je; j += 2) {
        int sa = __ldg(&g_csr[j]);
        int sb2 = __ldg(&g_csr[j + 1]);
        uint2 va = __ldg(&base[(size_t)sa * 32 + lane]);
        uint2 vb = __ldg(&base[(size_t)sb2 * 32 + lane]);
        float2 a0 = __half22float2(*(__half2*)&va.x);
        float2 a1v = __half22float2(*(__half2*)&va.y);
        float2 b0 = __half22float2(*(__half2*)&vb.x);
        float2 b1v = __half22float2(*(__half2*)&vb.y);
        ax += a0.x + b0.x; ay += a0.y + b0.y;
        az += a1v.x + b1v.x; aw += a1v.y + b1v.y;
    }
    if (j < je) {
        int sa = __ldg(&g_csr[j]);
        uint2 va = __ldg(&base[(size_t)sa * 32 + lane]);
        float2 a0 = __half22float2(*(__half2*)&va.x);
        float2 a1v = __half22float2(*(__half2*)&va.y);
        ax += a0.x; ay += a0.y; az += a1v.x; aw += a1v.y;
    }
    float iv = g_inv[node];
    float4 bb = __ldg((const float4*)b1 + lane);
    float4 r;
    r.x = fmaxf(iv * ax + bb.x, 0.f);
    r.y = fmaxf(iv * ay + bb.y, 0.f);
    r.z = fmaxf(iv * az + bb.z, 0.f);
    r.w = fmaxf(iv * aw + bb.w, 0.f);
    ((float4*)g_a1)[(size_t)node * 32 + lane] = r;
}

// ---------------------------------------------------------------------------
// agg2: warp per node, fp16 gather (uint = 2 halves/lane), fp32 accumulate.
// out[d] = inv[d]*(hs2[d] + sum_src hs2[src]) + b2     (out fp32)
// ---------------------------------------------------------------------------
__global__ __launch_bounds__(256) void k_agg2(float* __restrict__ out,
                                              const float* __restrict__ b2) {
    int node = blockIdx.x * 8 + (threadIdx.x >> 5);
    if (node >= N_NODES) return;
    int lane = threadIdx.x & 31;
    const uint32_t* base = (const uint32_t*)g_hs2h;  // 2 halves per lane

    uint32_t sv = __ldg(&base[(size_t)node * 32 + lane]);
    float2 acc = __half22float2(*(__half2*)&sv);

    int j  = g_ro[node];
    int je = g_ro[node + 1];
    for (; j + 1 < je; j += 2) {
        int sa = __ldg(&g_csr[j]);
        int sb2 = __ldg(&g_csr[j + 1]);
        uint32_t va = __ldg(&base[(size_t)sa * 32 + lane]);
        uint32_t vb = __ldg(&base[(size_t)sb2 * 32 + lane]);
        float2 a0 = __half22float2(*(__half2*)&va);
        float2 b0 = __half22float2(*(__half2*)&vb);
        acc.x += a0.x + b0.x; acc.y += a0.y + b0.y;
    }
    if (j < je) {
        int sa = __ldg(&g_csr[j]);
        uint32_t va = __ldg(&base[(size_t)sa * 32 + lane]);
        float2 a0 = __half22float2(*(__half2*)&va);
        acc.x += a0.x; acc.y += a0.y;
    }
    float iv = g_inv[node];
    float2 bb = __ldg((const float2*)b2 + lane);
    float2 r;
    r.x = iv * acc.x + bb.x;
    r.y = iv * acc.y + bb.y;
    ((float2*)out)[(size_t)node * 32 + lane] = r;
}

// ---------------------------------------------------------------------------
extern "C" void kernel_launch(void* const* d_in, const int* in_sizes, int n_in,
                              void* d_out, int out_size) {
    const float* x  = (const float*)d_in[0];
    const void*  ei = d_in[1];
    const float* W1 = (const float*)d_in[2];
    const float* b1 = (const float*)d_in[3];
    const float* W2 = (const float*)d_in[4];
    const float* b2 = (const float*)d_in[5];
    float* out = (float*)d_out;

    const int SCAN_BLOCKS = N_PAD / 256;   // 392
    const int SMEM1 = 2 * 128 * 136 * 2 + 2 * 128 * (128 + 8) * 2;  // 139264
    const int SMEM2 = 2 * 128 * 136 * 2 + 2 * 128 * (64 + 8) * 2;   // 106496

    cudaFuncSetAttribute(k_mgemm<128>, cudaFuncAttributeMaxDynamicSharedMemorySize, SMEM1);
    cudaFuncSetAttribute(k_mgemm<64>,  cudaFuncAttributeMaxDynamicSharedMemorySize, SMEM2);

    __half* hs1 = nullptr; cudaGetSymbolAddress((void**)&hs1, g_hs1h);
    float*  a1  = nullptr; cudaGetSymbolAddress((void**)&a1,  g_a1);
    __half* hs2 = nullptr; cudaGetSymbolAddress((void**)&hs2, g_hs2h);

    k_init  <<<(N_NODES + 255) / 256, 256>>>();
    k_detect<<<16, 256>>>((const long long*)ei);
    k_count <<<(N_EDGES + 255) / 256, 256>>>(ei);
    k_scan1 <<<SCAN_BLOCKS, 256>>>();
    k_scan2 <<<1, 512>>>(SCAN_BLOCKS);
    k_scan3 <<<SCAN_BLOCKS, 256>>>();
    k_fill  <<<(N_EDGES + 255) / 256, 256>>>(ei);

    k_mgemm<128><<<(N_NODES + 127) / 128, 256, SMEM1>>>(x, W1, hs1);
    k_agg1  <<<(N_NODES + 7) / 8, 256>>>(b1);
    k_mgemm<64> <<<(N_NODES + 127) / 128, 256, SMEM2>>>(a1, W2, hs2);
    k_agg2  <<<(N_NODES + 7) / 8, 256>>>(out, b2);
}

// round 6
// speedup vs baseline: 2.1309x; 1.0842x over previous
#include <cuda_runtime.h>
#include <cuda_bf16.h>
#include <cuda_fp16.h>
#include <cstdint>

#define N_NODES 100000
#define N_EDGES 1600000
#define IN_C    128
#define HID_C   128
#define OUT_C   64
#define N_PAD   100352          // 392*256 >= N_NODES+1

// Scratch (no allocations allowed -> __device__ globals)
__device__ __half g_hs1h[(size_t)N_NODES * HID_C]; // fp16 inv[s]*h1[s]
__device__ __half g_a1h [(size_t)N_NODES * HID_C]; // fp16 relu(inv*agg+b1)
__device__ __half g_hs2h[(size_t)N_NODES * OUT_C]; // fp16 inv[s]*h2[s]
__device__ int    g_deg [N_NODES];
__device__ float  g_inv [N_NODES];
__device__ int    g_ro  [N_PAD];
__device__ int    g_cur [N_PAD];
__device__ int    g_csr [N_EDGES];
__device__ int    g_bsum[512];
__device__ int    g_boff[512];

// ---------------------------------------------------------------------------
// helpers
// ---------------------------------------------------------------------------
__device__ __forceinline__ uint32_t smem_u32(const void* p) {
    uint32_t a;
    asm("{ .reg .u64 t; cvta.to.shared.u64 t, %1; cvt.u32.u64 %0, t; }" : "=r"(a) : "l"(p));
    return a;
}
__device__ __forceinline__ void ldm_x4(uint32_t* r, uint32_t addr) {
    asm volatile("ldmatrix.sync.aligned.m8n8.x4.shared.b16 {%0,%1,%2,%3}, [%4];"
                 : "=r"(r[0]), "=r"(r[1]), "=r"(r[2]), "=r"(r[3]) : "r"(addr));
}
__device__ __forceinline__ void ldm_x4t(uint32_t* r, uint32_t addr) {
    asm volatile("ldmatrix.sync.aligned.m8n8.x4.trans.shared.b16 {%0,%1,%2,%3}, [%4];"
                 : "=r"(r[0]), "=r"(r[1]), "=r"(r[2]), "=r"(r[3]) : "r"(addr));
}
__device__ __forceinline__ void mma_bf16(float* c, const uint32_t* a, const uint32_t* b) {
    asm volatile("mma.sync.aligned.m16n8k16.row.col.f32.bf16.bf16.f32 "
                 "{%0,%1,%2,%3}, {%4,%5,%6,%7}, {%8,%9}, {%0,%1,%2,%3};"
                 : "+f"(c[0]), "+f"(c[1]), "+f"(c[2]), "+f"(c[3])
                 : "r"(a[0]), "r"(a[1]), "r"(a[2]), "r"(a[3]), "r"(b[0]), "r"(b[1]));
}
__device__ __forceinline__ uint32_t pack_bf16(float a, float b, float& ra, float& rb) {
    __nv_bfloat16 ha = __float2bfloat16(a), hb = __float2bfloat16(b);
    ra = a - __bfloat162float(ha);
    rb = b - __bfloat162float(hb);
    return (uint32_t)__bfloat16_as_ushort(ha) | ((uint32_t)__bfloat16_as_ushort(hb) << 16);
}
__device__ __forceinline__ uint32_t pack_bf16_lo(float a, float b) {
    return (uint32_t)__bfloat16_as_ushort(__float2bfloat16(a))
         | ((uint32_t)__bfloat16_as_ushort(__float2bfloat16(b)) << 16);
}

// Per-block edge dtype sniff: reading int32 data as int64 packs two random
// indices into one word -> value out of [0, N_NODES) almost surely.
__device__ __forceinline__ int block_is32(const void* ei) {
    const long long* p = (const long long*)ei;
    int lane = threadIdx.x & 31;
    int bad = 0;
    if (threadIdx.x < 32) {
        long long v = p[lane];
        bad = (v < 0 || v >= N_NODES) ? 1 : 0;
    }
    __shared__ int sh_is32;
    if (threadIdx.x < 32) {
        unsigned m = __ballot_sync(0xFFFFFFFFu, bad);
        if (lane == 0) sh_is32 = (m != 0);
    }
    __syncthreads();
    return sh_is32;
}
__device__ __forceinline__ int edge_val(const void* ei, int is32, long long idx) {
    if (is32) return ((const int*)ei)[idx];
    return (int)(((const long long*)ei)[idx]);
}

// ---------------------------------------------------------------------------
// setup
// ---------------------------------------------------------------------------
__global__ void k_count(const void* __restrict__ ei) {
    int is32 = block_is32(ei);
    int e = blockIdx.x * blockDim.x + threadIdx.x;
    if (e < N_EDGES) {
        int d = edge_val(ei, is32, (long long)N_EDGES + e);
        atomicAdd(&g_deg[d], 1);
    }
}
__global__ void k_scan1() {
    __shared__ int sh[256];
    int t = threadIdx.x;
    int i = blockIdx.x * 256 + t;
    int v = (i < N_NODES) ? g_deg[i] : 0;
    if (i < N_NODES) g_inv[i] = rsqrtf((float)(v + 1));
    sh[t] = v; __syncthreads();
    #pragma unroll
    for (int off = 1; off < 256; off <<= 1) {
        int add = (t >= off) ? sh[t - off] : 0;
        __syncthreads();
        sh[t] += add;
        __syncthreads();
    }
    g_ro[i] = sh[t] - v;
    if (t == 255) g_bsum[blockIdx.x] = sh[255];
}
__global__ void k_scan2(int nblocks) {
    __shared__ int sh[512];
    int t = threadIdx.x;
    int v = (t < nblocks) ? g_bsum[t] : 0;
    sh[t] = v; __syncthreads();
    #pragma unroll
    for (int off = 1; off < 512; off <<= 1) {
        int add = (t >= off) ? sh[t - off] : 0;
        __syncthreads();
        sh[t] += add;
        __syncthreads();
    }
    g_boff[t] = sh[t] - v;
}
__global__ void k_scan3() {
    int i = blockIdx.x * 256 + threadIdx.x;
    int v = g_ro[i] + g_boff[blockIdx.x];
    g_ro[i]  = v;
    g_cur[i] = v;
}
__global__ void k_fill(const void* __restrict__ ei) {
    int is32 = block_is32(ei);
    int e = blockIdx.x * blockDim.x + threadIdx.x;
    if (e < N_EDGES) {
        int s = edge_val(ei, is32, e);
        int d = edge_val(ei, is32, (long long)N_EDGES + e);
        int pos = atomicAdd(&g_cur[d], 1);
        g_csr[pos] = s;
    }
}

// ---------------------------------------------------------------------------
// Warp-MMA split-bf16 GEMM: Out[row,0:NC] = inv[row] * (A[row,0:128] @ W[0:128,0:NC])
// A fp32 or fp16; Out fp16. 3 passes: Ahi*Bhi + Ahi*Blo + Alo*Bhi.
// ---------------------------------------------------------------------------
template<int NC, typename TIN>
__global__ __launch_bounds__(256, 1) void k_mgemm(const TIN* __restrict__ A,
                                                  const float* __restrict__ W,
                                                  __half* __restrict__ Out) {
    constexpr int WN   = NC / 2;
    constexpr int NT   = WN / 8;
    constexpr int AST  = 136;
    constexpr int BST  = NC + 8;
    constexpr int A_HI = 0;
    constexpr int A_LO = 128 * AST * 2;
    constexpr int B_HI = 2 * 128 * AST * 2;
    constexpr int B_LO = B_HI + 128 * BST * 2;

    extern __shared__ char smem[];
    const uint32_t sb = smem_u32(smem);
    const int tid = threadIdx.x, wid = tid >> 5, lane = tid & 31;
    const int blockRow = blockIdx.x * 128;

    // ---- fill A (hi/lo bf16) ----
    for (int idx = tid; idx < 128 * 64; idx += 256) {
        int r = idx >> 6, k2 = (idx & 63) << 1;
        int row = blockRow + r;
        float a0 = 0.f, a1 = 0.f;
        if (row < N_NODES) {
            if constexpr (sizeof(TIN) == 4) {
                float2 v = *(const float2*)(A + (size_t)row * 128 + k2);
                a0 = v.x; a1 = v.y;
            } else {
                __half2 h = *(const __half2*)(A + (size_t)row * 128 + k2);
                float2 v = __half22float2(h);
                a0 = v.x; a1 = v.y;
            }
        }
        float l0, l1;
        uint32_t hi = pack_bf16(a0, a1, l0, l1);
        uint32_t lo = pack_bf16_lo(l0, l1);
        uint32_t off = (uint32_t)(r * AST + k2) * 2;
        *(uint32_t*)(smem + A_HI + off) = hi;
        *(uint32_t*)(smem + A_LO + off) = lo;
    }
    // ---- fill B (hi/lo), coalesced from W[k][n] ----
    for (int idx = tid; idx < 128 * (NC / 2); idx += 256) {
        int k = idx / (NC / 2), n2 = (idx % (NC / 2)) << 1;
        float2 w = *(const float2*)(W + (size_t)k * NC + n2);
        float l0, l1;
        uint32_t hi = pack_bf16(w.x, w.y, l0, l1);
        uint32_t lo = pack_bf16_lo(l0, l1);
        uint32_t off = (uint32_t)(k * BST + n2) * 2;
        *(uint32_t*)(smem + B_HI + off) = hi;
        *(uint32_t*)(smem + B_LO + off) = lo;
    }
    __syncthreads();

    const int wm = (wid & 3) * 32;
    const int wn = (wid >> 2) * WN;

    float acc[2][NT][4];
    #pragma unroll
    for (int mt = 0; mt < 2; mt++)
        #pragma unroll
        for (int nt = 0; nt < NT; nt++)
            #pragma unroll
            for (int i = 0; i < 4; i++) acc[mt][nt][i] = 0.f;

    const int laA = lane & 15, lbA = lane >> 4;
    const int rB = (((lane >> 3) & 1) << 3) + (lane & 7);
    const int cB = (lane >> 4) << 3;

    #pragma unroll
    for (int ks = 0; ks < 8; ks++) {
        const int k0 = ks * 16;
        uint32_t a_hi[2][4], a_lo[2][4], bh[NT][2], bl[NT][2];
        #pragma unroll
        for (int mt = 0; mt < 2; mt++) {
            uint32_t addr = sb + A_HI + (uint32_t)((wm + mt * 16 + laA) * AST + k0 + lbA * 8) * 2;
            ldm_x4(a_hi[mt], addr);
            ldm_x4(a_lo[mt], addr + (A_LO - A_HI));
        }
        #pragma unroll
        for (int nt2 = 0; nt2 < NT / 2; nt2++) {
            uint32_t addr = sb + B_HI + (uint32_t)((k0 + rB) * BST + wn + nt2 * 16 + cB) * 2;
            uint32_t t[4];
            ldm_x4t(t, addr);
            bh[2 * nt2][0] = t[0]; bh[2 * nt2][1] = t[1];
            bh[2 * nt2 + 1][0] = t[2]; bh[2 * nt2 + 1][1] = t[3];
            ldm_x4t(t, addr + (B_LO - B_HI));
            bl[2 * nt2][0] = t[0]; bl[2 * nt2][1] = t[1];
            bl[2 * nt2 + 1][0] = t[2]; bl[2 * nt2 + 1][1] = t[3];
        }
        #pragma unroll
        for (int mt = 0; mt < 2; mt++)
            #pragma unroll
            for (int nt = 0; nt < NT; nt++) {
                mma_bf16(acc[mt][nt], a_hi[mt], bh[nt]);
                mma_bf16(acc[mt][nt], a_hi[mt], bl[nt]);
                mma_bf16(acc[mt][nt], a_lo[mt], bh[nt]);
            }
    }

    // ---- epilogue: scale by inv[row], half2 stores ----
    #pragma unroll
    for (int mt = 0; mt < 2; mt++) {
        int row0 = blockRow + wm + mt * 16 + (lane >> 2);
        int row1 = row0 + 8;
        float iv0 = (row0 < N_NODES) ? g_inv[row0] : 0.f;
        float iv1 = (row1 < N_NODES) ? g_inv[row1] : 0.f;
        #pragma unroll
        for (int nt = 0; nt < NT; nt++) {
            int col = wn + nt * 8 + (lane & 3) * 2;
            if (row0 < N_NODES) {
                __half2 h = __floats2half2_rn(iv0 * acc[mt][nt][0], iv0 * acc[mt][nt][1]);
                *(__half2*)(Out + (size_t)row0 * NC + col) = h;
            }
            if (row1 < N_NODES) {
                __half2 h = __floats2half2_rn(iv1 * acc[mt][nt][2], iv1 * acc[mt][nt][3]);
                *(__half2*)(Out + (size_t)row1 * NC + col) = h;
            }
        }
    }
}

// ---------------------------------------------------------------------------
// agg1: half-warp (16 lanes x uint4 = 256B) per node, unroll-4, fp32 accum.
// a1h[d] = fp16( relu(inv[d]*(hs1[d] + sum_src hs1[src]) + b1) )
// ---------------------------------------------------------------------------
__global__ __launch_bounds__(256) void k_agg1(const float* __restrict__ b1) {
    int node = blockIdx.x * 16 + (threadIdx.x >> 4);
    if (node >= N_NODES) return;
    int l = threadIdx.x & 15;                  // 8 channels per lane
    const uint4* base = (const uint4*)g_hs1h;  // 16 uint4 per row

    float a[8];
    {
        uint4 sv = __ldg(&base[(size_t)node * 16 + l]);
        float2 p0 = __half22float2(*(__half2*)&sv.x);
        float2 p1 = __half22float2(*(__half2*)&sv.y);
        float2 p2 = __half22float2(*(__half2*)&sv.z);
        float2 p3 = __half22float2(*(__half2*)&sv.w);
        a[0]=p0.x; a[1]=p0.y; a[2]=p1.x; a[3]=p1.y; a[4]=p2.x; a[5]=p2.y; a[6]=p3.x; a[7]=p3.y;
    }
    int j  = g_ro[node];
    int je = g_ro[node + 1];
    for (; j + 3 < je; j += 4) {
        int s0 = __ldg(&g_csr[j]),     s1 = __ldg(&g_csr[j + 1]);
        int s2 = __ldg(&g_csr[j + 2]), s3 = __ldg(&g_csr[j + 3]);
        uint4 v0 = __ldg(&base[(size_t)s0 * 16 + l]);
        uint4 v1 = __ldg(&base[(size_t)s1 * 16 + l]);
        uint4 v2 = __ldg(&base[(size_t)s2 * 16 + l]);
        uint4 v3 = __ldg(&base[(size_t)s3 * 16 + l]);
        #pragma unroll
        for (int q = 0; q < 4; q++) {
            uint4 v = (q == 0) ? v0 : (q == 1) ? v1 : (q == 2) ? v2 : v3;
            float2 p0 = __half22float2(*(__half2*)&v.x);
            float2 p1 = __half22float2(*(__half2*)&v.y);
            float2 p2 = __half22float2(*(__half2*)&v.z);
            float2 p3 = __half22float2(*(__half2*)&v.w);
            a[0]+=p0.x; a[1]+=p0.y; a[2]+=p1.x; a[3]+=p1.y;
            a[4]+=p2.x; a[5]+=p2.y; a[6]+=p3.x; a[7]+=p3.y;
        }
    }
    for (; j < je; j++) {
        int s0 = __ldg(&g_csr[j]);
        uint4 v = __ldg(&base[(size_t)s0 * 16 + l]);
        float2 p0 = __half22float2(*(__half2*)&v.x);
        float2 p1 = __half22float2(*(__half2*)&v.y);
        float2 p2 = __half22float2(*(__half2*)&v.z);
        float2 p3 = __half22float2(*(__half2*)&v.w);
        a[0]+=p0.x; a[1]+=p0.y; a[2]+=p1.x; a[3]+=p1.y;
        a[4]+=p2.x; a[5]+=p2.y; a[6]+=p3.x; a[7]+=p3.y;
    }
    float iv = g_inv[node];
    float4 bb0 = __ldg((const float4*)b1 + l * 2);
    float4 bb1 = __ldg((const float4*)b1 + l * 2 + 1);
    float r[8];
    r[0]=fmaxf(iv*a[0]+bb0.x,0.f); r[1]=fmaxf(iv*a[1]+bb0.y,0.f);
    r[2]=fmaxf(iv*a[2]+bb0.z,0.f); r[3]=fmaxf(iv*a[3]+bb0.w,0.f);
    r[4]=fmaxf(iv*a[4]+bb1.x,0.f); r[5]=fmaxf(iv*a[5]+bb1.y,0.f);
    r[6]=fmaxf(iv*a[6]+bb1.z,0.f); r[7]=fmaxf(iv*a[7]+bb1.w,0.f);
    uint4 o;
    *(__half2*)&o.x = __floats2half2_rn(r[0], r[1]);
    *(__half2*)&o.y = __floats2half2_rn(r[2], r[3]);
    *(__half2*)&o.z = __floats2half2_rn(r[4], r[5]);
    *(__half2*)&o.w = __floats2half2_rn(r[6], r[7]);
    ((uint4*)g_a1h)[(size_t)node * 16 + l] = o;
}

// ---------------------------------------------------------------------------
// agg2: eighth-warp (8 lanes x uint4 = 128B) per node, unroll-4, fp32 accum.
// out[d] = inv[d]*(hs2[d] + sum_src hs2[src]) + b2     (out fp32)
// ---------------------------------------------------------------------------
__global__ __launch_bounds__(256) void k_agg2(float* __restrict__ out,
                                              const float* __restrict__ b2) {
    int node = blockIdx.x * 32 + (threadIdx.x >> 3);
    if (node >= N_NODES) return;
    int l = threadIdx.x & 7;                   // 8 channels per lane
    const uint4* base = (const uint4*)g_hs2h;  // 8 uint4 per row

    float a[8];
    {
        uint4 sv = __ldg(&base[(size_t)node * 8 + l]);
        float2 p0 = __half22float2(*(__half2*)&sv.x);
        float2 p1 = __half22float2(*(__half2*)&sv.y);
        float2 p2 = __half22float2(*(__half2*)&sv.z);
        float2 p3 = __half22float2(*(__half2*)&sv.w);
        a[0]=p0.x; a[1]=p0.y; a[2]=p1.x; a[3]=p1.y; a[4]=p2.x; a[5]=p2.y; a[6]=p3.x; a[7]=p3.y;
    }
    int j  = g_ro[node];
    int je = g_ro[node + 1];
    for (; j + 3 < je; j += 4) {
        int s0 = __ldg(&g_csr[j]),     s1 = __ldg(&g_csr[j + 1]);
        int s2 = __ldg(&g_csr[j + 2]), s3 = __ldg(&g_csr[j + 3]);
        uint4 v0 = __ldg(&base[(size_t)s0 * 8 + l]);
        uint4 v1 = __ldg(&base[(size_t)s1 * 8 + l]);
        uint4 v2 = __ldg(&base[(size_t)s2 * 8 + l]);
        uint4 v3 = __ldg(&base[(size_t)s3 * 8 + l]);
        #pragma unroll
        for (int q = 0; q < 4; q++) {
            uint4 v = (q == 0) ? v0 : (q == 1) ? v1 : (q == 2) ? v2 : v3;
            float2 p0 = __half22float2(*(__half2*)&v.x);
            float2 p1 = __half22float2(*(__half2*)&v.y);
            float2 p2 = __half22float2(*(__half2*)&v.z);
            float2 p3 = __half22float2(*(__half2*)&v.w);
            a[0]+=p0.x; a[1]+=p0.y; a[2]+=p1.x; a[3]+=p1.y;
            a[4]+=p2.x; a[5]+=p2.y; a[6]+=p3.x; a[7]+=p3.y;
        }
    }
    for (; j < je; j++) {
        int s0 = __ldg(&g_csr[j]);
        uint4 v = __ldg(&base[(size_t)s0 * 8 + l]);
        float2 p0 = __half22float2(*(__half2*)&v.x);
        float2 p1 = __half22float2(*(__half2*)&v.y);
        float2 p2 = __half22float2(*(__half2*)&v.z);
        float2 p3 = __half22float2(*(__half2*)&v.w);
        a[0]+=p0.x; a[1]+=p0.y; a[2]+=p1.x; a[3]+=p1.y;
        a[4]+=p2.x; a[5]+=p2.y; a[6]+=p3.x; a[7]+=p3.y;
    }
    float iv = g_inv[node];
    float4 bb0 = __ldg((const float4*)b2 + l * 2);
    float4 bb1 = __ldg((const float4*)b2 + l * 2 + 1);
    float4 o0, o1;
    o0.x = iv*a[0]+bb0.x; o0.y = iv*a[1]+bb0.y; o0.z = iv*a[2]+bb0.z; o0.w = iv*a[3]+bb0.w;
    o1.x = iv*a[4]+bb1.x; o1.y = iv*a[5]+bb1.y; o1.z = iv*a[6]+bb1.z; o1.w = iv*a[7]+bb1.w;
    float4* ob = (float4*)(out + (size_t)node * OUT_C + l * 8);
    ob[0] = o0; ob[1] = o1;
}

// ---------------------------------------------------------------------------
extern "C" void kernel_launch(void* const* d_in, const int* in_sizes, int n_in,
                              void* d_out, int out_size) {
    const float* x  = (const float*)d_in[0];
    const void*  ei = d_in[1];
    const float* W1 = (const float*)d_in[2];
    const float* b1 = (const float*)d_in[3];
    const float* W2 = (const float*)d_in[4];
    const float* b2 = (const float*)d_in[5];
    float* out = (float*)d_out;

    const int SCAN_BLOCKS = N_PAD / 256;   // 392
    const int SMEM1 = 2 * 128 * 136 * 2 + 2 * 128 * (128 + 8) * 2;  // 139264
    const int SMEM2 = 2 * 128 * 136 * 2 + 2 * 128 * (64 + 8) * 2;   // 106496

    cudaFuncSetAttribute((const void*)k_mgemm<128, float>,
                         cudaFuncAttributeMaxDynamicSharedMemorySize, SMEM1);
    cudaFuncSetAttribute((const void*)k_mgemm<64, __half>,
                         cudaFuncAttributeMaxDynamicSharedMemorySize, SMEM2);

    __half* hs1 = nullptr; cudaGetSymbolAddress((void**)&hs1, g_hs1h);
    __half* a1  = nullptr; cudaGetSymbolAddress((void**)&a1,  g_a1h);
    __half* hs2 = nullptr; cudaGetSymbolAddress((void**)&hs2, g_hs2h);
    int* degp   = nullptr; cudaGetSymbolAddress((void**)&degp, g_deg);

    cudaMemsetAsync(degp, 0, N_NODES * sizeof(int));
    k_count <<<(N_EDGES + 255) / 256, 256>>>(ei);
    k_scan1 <<<SCAN_BLOCKS, 256>>>();
    k_scan2 <<<1, 512>>>(SCAN_BLOCKS);
    k_scan3 <<<SCAN_BLOCKS, 256>>>();
    k_fill  <<<(N_EDGES + 255) / 256, 256>>>(ei);

    k_mgemm<128, float><<<(N_NODES + 127) / 128, 256, SMEM1>>>(x, W1, hs1);
    k_agg1  <<<(N_NODES + 15) / 16, 256>>>(b1);
    k_mgemm<64, __half><<<(N_NODES + 127) / 128, 256, SMEM2>>>(a1, W2, hs2);
    k_agg2  <<<(N_NODES + 31) / 32, 256>>>(out, b2);
}